// round 3
// baseline (speedup 1.0000x reference)
#include <cuda_runtime.h>
#include <cstddef>
#include <cstdint>

// ---------------------------------------------------------------------------
// Sparse 3D UNet forward.  Tiled-GEMM sparse conv, f32x2 packed math.
//   out[i, cout] = epi( sum_k sum_cin feat[nbr[i,k], cin] * W[k,cin,cout] )
// Feature tile stored TRANSPOSED in smem: sfeat[cin][row] so each thread's
// row-pair loads as a native f32x2.  W optionally pre-duplicated as (w,w)
// u64 pairs so the inner loop is pure LDS128 + FFMA2.
// ---------------------------------------------------------------------------

__device__ float g_pool[96u * 1024u * 1024u];   // 384 MB scratch (static: legal)

using ull = unsigned long long;

__device__ __forceinline__ ull pack2(float lo, float hi) {
    ull r; asm("mov.b64 %0, {%1,%2};" : "=l"(r) : "f"(lo), "f"(hi)); return r;
}
__device__ __forceinline__ void unpack2(ull v, float& lo, float& hi) {
    asm("mov.b64 {%0,%1}, %2;" : "=f"(lo), "=f"(hi) : "l"(v));
}
__device__ __forceinline__ ull ffma2(ull a, ull b, ull c) {
    ull d; asm("fma.rn.f32x2 %0, %1, %2, %3;" : "=l"(d) : "l"(a), "l"(b), "l"(c));
    return d;
}

template <int CIN, int COUT>
__global__ void __launch_bounds__(256)
spconv_gemm(const float* __restrict__ feat, int ldf,
            const int* __restrict__ nbr,
            const float* __restrict__ W,      // (27, CIN, COUT)
            const float* __restrict__ sb,     // scale[COUT], bias[COUT]
            const float* __restrict__ resid, int ldr,
            const float* __restrict__ red,   int ldred,
            float* __restrict__ out, int ldo, int N)
{
    constexpr int TN = 4;
    constexpr int TX = COUT / TN;        // 8 or 16
    constexpr int TY = 256 / TX;         // 32 or 16
    constexpr int BM = 128;
    constexpr int TM = BM / TY;          // 4 or 8
    constexpr int TP = TM / 2;           // row pairs: 2 or 4
    constexpr int C4 = CIN / 4;
    constexpr bool DUP = (CIN * (size_t)COUT <= 2048);

    __shared__ int   snbr[27][BM];
    __shared__ float sfeat[CIN][BM];             // transposed
    __shared__ ull   sW2[DUP ? CIN : 1][DUP ? COUT : 1];   // duplicated pairs
    __shared__ float sWf[DUP ? 1 : CIN][DUP ? 1 : COUT];
    __shared__ int   khit[27];

    const int tid  = threadIdx.x;
    const int tx   = tid % TX;
    const int ty   = tid / TX;
    const int row0 = blockIdx.x * BM;

    // Stage neighbor indices (coalesced)
    for (int e = tid; e < BM * 27; e += 256) {
        int r = e / 27, k = e % 27;
        int g = row0 + r;
        snbr[k][r] = (g < N) ? nbr[(size_t)g * 27 + k] : -1;
    }
    __syncthreads();
    if (tid < 27) {
        int h = 0;
        for (int r = 0; r < BM && !h; ++r) h = (snbr[tid][r] >= 0);
        khit[tid] = h;
    }
    __syncthreads();

    ull acc[TP][TN];
#pragma unroll
    for (int p = 0; p < TP; ++p)
#pragma unroll
        for (int j = 0; j < TN; ++j) acc[p][j] = 0ull;

    for (int k = 0; k < 27; ++k) {
        if (!khit[k]) continue;

        // Gather features, store transposed (conflict-free: lanes span rows)
#pragma unroll
        for (int u = tid; u < BM * C4; u += 256) {
            int r  = u & (BM - 1);
            int c4 = u >> 7;
            int idx = snbr[k][r];
            float4 v = make_float4(0.f, 0.f, 0.f, 0.f);
            if (idx >= 0)
                v = *(const float4*)(feat + (size_t)idx * ldf + c4 * 4);
            sfeat[c4 * 4 + 0][r] = v.x;
            sfeat[c4 * 4 + 1][r] = v.y;
            sfeat[c4 * 4 + 2][r] = v.z;
            sfeat[c4 * 4 + 3][r] = v.w;
        }
        // Stage W[k]
        if (DUP) {
#pragma unroll
            for (int u = tid; u < CIN * COUT / 4; u += 256) {
                int c  = u / (COUT / 4);
                int n4 = u % (COUT / 4);
                float4 w = *(const float4*)(W + (size_t)k * CIN * COUT
                                              + (size_t)c * COUT + n4 * 4);
                sW2[c][n4 * 4 + 0] = pack2(w.x, w.x);
                sW2[c][n4 * 4 + 1] = pack2(w.y, w.y);
                sW2[c][n4 * 4 + 2] = pack2(w.z, w.z);
                sW2[c][n4 * 4 + 3] = pack2(w.w, w.w);
            }
        } else {
#pragma unroll
            for (int u = tid; u < CIN * COUT / 4; u += 256) {
                int c  = u / (COUT / 4);
                int n4 = u % (COUT / 4);
                *(float4*)(&sWf[c][n4 * 4]) =
                    *(const float4*)(W + (size_t)k * CIN * COUT
                                       + (size_t)c * COUT + n4 * 4);
            }
        }
        __syncthreads();

#pragma unroll 4
        for (int cin = 0; cin < CIN; ++cin) {
            // feature row-pairs: native f32x2 loads (contiguous rows)
            ull f2[TP];
            const ull* frow = (const ull*)(&sfeat[cin][0]) + (ty * TM) / 2;
#pragma unroll
            for (int p = 0; p < TP; ++p) f2[p] = frow[p];

            ull w2[TN];
            if (DUP) {
#pragma unroll
                for (int j = 0; j < TN; ++j) w2[j] = sW2[cin][tx * TN + j];
            } else {
                float4 wv = *(const float4*)(&sWf[cin][tx * TN]);
                w2[0] = pack2(wv.x, wv.x);
                w2[1] = pack2(wv.y, wv.y);
                w2[2] = pack2(wv.z, wv.z);
                w2[3] = pack2(wv.w, wv.w);
            }
#pragma unroll
            for (int p = 0; p < TP; ++p)
#pragma unroll
                for (int j = 0; j < TN; ++j)
                    acc[p][j] = ffma2(f2[p], w2[j], acc[p][j]);
        }
        __syncthreads();
    }

    // Epilogue: *scale + bias (+resid) -> relu (+pair-reduce)
    float sc[TN], bi[TN];
#pragma unroll
    for (int j = 0; j < TN; ++j) {
        sc[j] = sb[tx * TN + j];
        bi[j] = sb[COUT + tx * TN + j];
    }

#pragma unroll
    for (int p = 0; p < TP; ++p) {
        float v0[TN], v1[TN];
#pragma unroll
        for (int j = 0; j < TN; ++j) unpack2(acc[p][j], v0[j], v1[j]);

#pragma unroll
        for (int half = 0; half < 2; ++half) {
            float* v = half ? v1 : v0;
            int r = row0 + ty * TM + 2 * p + half;
            if (r >= N) continue;
#pragma unroll
            for (int j = 0; j < TN; ++j) v[j] = v[j] * sc[j] + bi[j];
            if (resid) {
                float4 rr = *(const float4*)(resid + (size_t)r * ldr + tx * TN);
                v[0] += rr.x; v[1] += rr.y; v[2] += rr.z; v[3] += rr.w;
            }
#pragma unroll
            for (int j = 0; j < TN; ++j) v[j] = fmaxf(v[j], 0.f);
            if (red) {
                float4 ra = *(const float4*)(red + (size_t)r * ldred + 2 * tx * TN);
                float4 rb = *(const float4*)(red + (size_t)r * ldred + 2 * tx * TN + 4);
                v[0] += ra.x + ra.y; v[1] += ra.z + ra.w;
                v[2] += rb.x + rb.y; v[3] += rb.z + rb.w;
            }
            *(float4*)(out + (size_t)r * ldo + tx * TN) =
                make_float4(v[0], v[1], v[2], v[3]);
        }
    }
}

template <int CIN, int COUT>
static void conv_launch(const float* feat, int ldf, const int* nbr,
                        const float* W, const float* sb,
                        const float* resid, int ldr,
                        const float* red, int ldred,
                        float* out, int ldo, int N)
{
    const int grid = (N + 127) / 128;
    spconv_gemm<CIN, COUT><<<grid, 256>>>(
        feat, ldf, nbr, W, sb, resid, ldr, red, ldred, out, ldo, N);
}

extern "C" void kernel_launch(void* const* d_in, const int* in_sizes, int n_in,
                              void* d_out, int out_size)
{
    const float* voxel  = (const float*)d_in[0];
    const float* Win    = (const float*)d_in[1];
    const float* W32    = (const float*)d_in[2];
    const float* W64    = (const float*)d_in[3];
    const float* Wd3    = (const float*)d_in[4];
    const float* W6432  = (const float*)d_in[5];
    const float* W12864 = (const float*)d_in[6];
    const float* bn32   = (const float*)d_in[7];
    const float* bn64   = (const float*)d_in[8];
    const int* nbr1  = (const int*)d_in[9];
    const int* nbr2  = (const int*)d_in[10];
    const int* nbr3  = (const int*)d_in[11];
    const int* nbr4  = (const int*)d_in[12];
    const int* nbrd2 = (const int*)d_in[13];
    const int* nbrd3 = (const int*)d_in[14];
    const int* nbrd4 = (const int*)d_in[15];
    const int* nbri4 = (const int*)d_in[16];
    const int* nbri3 = (const int*)d_in[17];
    const int* nbri2 = (const int*)d_in[18];

    const int N1 = in_sizes[9]  / 27;
    const int N2 = in_sizes[10] / 27;
    const int N3 = in_sizes[11] / 27;
    const int N4 = in_sizes[12] / 27;

    float* pool = nullptr;
    cudaGetSymbolAddress((void**)&pool, g_pool);

    size_t o = 0;
    auto take = [&](size_t n) { size_t r = o; o += (n + 255) & ~(size_t)255; return r; };
    float* A    = pool + take((size_t)N1 * 32);
    float* X1   = pool + take((size_t)N1 * 32);
    float* cat1 = pool + take((size_t)N1 * 64);
    float* C    = pool + take((size_t)N2 * 32);
    float* Dm   = pool + take((size_t)N2 * 32);
    float* X2   = pool + take((size_t)N2 * 32);
    float* cat2 = pool + take((size_t)N2 * 64);
    float* Fm   = pool + take((size_t)N3 * 64);
    float* G    = pool + take((size_t)N3 * 64);
    float* X3   = pool + take((size_t)N3 * 64);
    float* cat3 = pool + take((size_t)N3 * 128);
    float* I    = pool + take((size_t)N4 * 64);
    float* J    = pool + take((size_t)N4 * 64);
    float* cat4 = pool + take((size_t)N4 * 128);

    float* outp = (float*)d_out;

    const size_t S32   = 27u * 32 * 32;
    const size_t S64   = 27u * 64 * 64;
    const size_t S6432 = 27u * 64 * 32;
    const size_t S1286 = 27u * 128 * 64;

    // ---- Encoder ----
    conv_launch<4, 32>(voxel, 4, nbr1, Win, bn32 + 0 * 64, nullptr, 0, nullptr, 0, A, 32, N1);
    conv_launch<32, 32>(A, 32, nbr1, W32 + 0 * S32, bn32 + 1 * 64, nullptr, 0, nullptr, 0, X1, 32, N1);
    conv_launch<32, 32>(X1, 32, nbrd2, W32 + 1 * S32, bn32 + 2 * 64, nullptr, 0, nullptr, 0, C, 32, N2);
    conv_launch<32, 32>(C, 32, nbr2, W32 + 2 * S32, bn32 + 3 * 64, nullptr, 0, nullptr, 0, Dm, 32, N2);
    conv_launch<32, 32>(Dm, 32, nbr2, W32 + 3 * S32, bn32 + 4 * 64, nullptr, 0, nullptr, 0, X2, 32, N2);
    conv_launch<32, 64>(X2, 32, nbrd3, Wd3, bn64 + 0 * 128, nullptr, 0, nullptr, 0, Fm, 64, N3);
    conv_launch<64, 64>(Fm, 64, nbr3, W64 + 0 * S64, bn64 + 1 * 128, nullptr, 0, nullptr, 0, G, 64, N3);
    conv_launch<64, 64>(G, 64, nbr3, W64 + 1 * S64, bn64 + 2 * 128, nullptr, 0, nullptr, 0, X3, 64, N3);
    conv_launch<64, 64>(X3, 64, nbrd4, W64 + 2 * S64, bn64 + 3 * 128, nullptr, 0, nullptr, 0, I, 64, N4);
    conv_launch<64, 64>(I, 64, nbr4, W64 + 3 * S64, bn64 + 4 * 128, nullptr, 0, nullptr, 0, J, 64, N4);
    conv_launch<64, 64>(J, 64, nbr4, W64 + 4 * S64, bn64 + 5 * 128, nullptr, 0, nullptr, 0, cat4, 128, N4);

    // ---- Bottleneck ----
    conv_launch<64, 64>(cat4, 128, nbr4, W64 + 5 * S64, bn64 + 6 * 128, nullptr, 0, nullptr, 0, I, 64, N4);
    conv_launch<64, 64>(I, 64, nbr4, W64 + 6 * S64, bn64 + 7 * 128, cat4, 128, nullptr, 0, cat4 + 64, 128, N4);
    conv_launch<128, 64>(cat4, 128, nbr4, W12864 + 0 * S1286, bn64 + 11 * 128, nullptr, 0, cat4, 128, J, 64, N4);

    // ---- Decoder level 3 ----
    conv_launch<64, 64>(J, 64, nbri4, W64 + 7 * S64, bn64 + 8 * 128, nullptr, 0, nullptr, 0, cat3, 128, N3);
    conv_launch<64, 64>(X3, 64, nbr3, W64 + 8 * S64, bn64 + 9 * 128, nullptr, 0, nullptr, 0, Fm, 64, N3);
    conv_launch<64, 64>(Fm, 64, nbr3, W64 + 9 * S64, bn64 + 10 * 128, X3, 64, nullptr, 0, cat3 + 64, 128, N3);
    conv_launch<128, 64>(cat3, 128, nbr3, W12864 + 1 * S1286, bn64 + 12 * 128, nullptr, 0, cat3, 128, G, 64, N3);

    // ---- Decoder level 2 ----
    conv_launch<64, 32>(G, 64, nbri3, W6432 + 0 * S6432, bn32 + 11 * 64, nullptr, 0, nullptr, 0, cat2, 64, N2);
    conv_launch<32, 32>(X2, 32, nbr2, W32 + 4 * S32, bn32 + 5 * 64, nullptr, 0, nullptr, 0, C, 32, N2);
    conv_launch<32, 32>(C, 32, nbr2, W32 + 5 * S32, bn32 + 6 * 64, X2, 32, nullptr, 0, cat2 + 32, 64, N2);
    conv_launch<64, 32>(cat2, 64, nbr2, W6432 + 1 * S6432, bn32 + 12 * 64, nullptr, 0, cat2, 64, Dm, 32, N2);

    // ---- Decoder level 1 ----
    conv_launch<32, 32>(Dm, 32, nbri2, W32 + 6 * S32, bn32 + 7 * 64, nullptr, 0, nullptr, 0, cat1, 64, N1);
    conv_launch<32, 32>(X1, 32, nbr1, W32 + 7 * S32, bn32 + 8 * 64, nullptr, 0, nullptr, 0, A, 32, N1);
    conv_launch<32, 32>(A, 32, nbr1, W32 + 8 * S32, bn32 + 9 * 64, X1, 32, nullptr, 0, cat1 + 32, 64, N1);
    conv_launch<64, 32>(cat1, 64, nbr1, W6432 + 2 * S6432, bn32 + 13 * 64, nullptr, 0, cat1, 64, A, 32, N1);

    // ---- Head ----
    conv_launch<32, 32>(A, 32, nbr1, W32 + 9 * S32, bn32 + 10 * 64, nullptr, 0, nullptr, 0, outp, 32, N1);
}

// round 4
// speedup vs baseline: 1.3567x; 1.3567x over previous
#include <cuda_runtime.h>
#include <cstddef>
#include <cstdint>

// ---------------------------------------------------------------------------
// Sparse 3D UNet forward.  cp.async double-buffered sparse-conv GEMM.
//   out[i, cout] = epi( sum_k sum_cin feat[nbr[i,k], cin] * W[k,cin,cout] )
// Pipeline over (k, channel-chunk): stage s+1 via cp.async (zero-fill for
// missing neighbors) while computing stage s.  f32x2 packed accumulation.
// ---------------------------------------------------------------------------

__device__ float g_pool[96u * 1024u * 1024u];   // 384 MB scratch (static: legal)

using ull = unsigned long long;

__device__ __forceinline__ ull pack2(float lo, float hi) {
    ull r; asm("mov.b64 %0, {%1,%2};" : "=l"(r) : "f"(lo), "f"(hi)); return r;
}
__device__ __forceinline__ void unpack2(ull v, float& lo, float& hi) {
    asm("mov.b64 {%0,%1}, %2;" : "=f"(lo), "=f"(hi) : "l"(v));
}
__device__ __forceinline__ ull ffma2(ull a, ull b, ull c) {
    ull d; asm("fma.rn.f32x2 %0, %1, %2, %3;" : "=l"(d) : "l"(a), "l"(b), "l"(c));
    return d;
}
__device__ __forceinline__ void cp_async16(uint32_t dst, const void* src, int nbytes) {
    asm volatile("cp.async.cg.shared.global [%0], [%1], 16, %2;"
                 :: "r"(dst), "l"(src), "r"(nbytes));
}
__device__ __forceinline__ void cp_commit() {
    asm volatile("cp.async.commit_group;");
}
template <int NG> __device__ __forceinline__ void cp_wait() {
    asm volatile("cp.async.wait_group %0;" :: "n"(NG));
}

template <int CIN, int COUT, int BM>
struct SpCfg {
    static constexpr int CK  = (CIN < 32) ? CIN : 32;
    static constexpr int NCH = CIN / CK;
    static constexpr int SP  = CK + 4;            // padded row stride (floats)
    static constexpr int VR  = CK / 4;            // 16B vectors per row chunk
    static constexpr int TN  = 4;
    static constexpr int TX  = COUT / TN;         // 8 or 16
    static constexpr int TY  = 256 / TX;          // 32 or 16
    static constexpr int TM  = BM / TY;           // 4 or 8
    static constexpr int TP  = TM / 2;
    static constexpr int SMEM_BYTES =
        (2 * BM * SP + 2 * CK * COUT) * 4 + 27 * BM * 4 + 64 * 4;
};

template <int CIN, int COUT, int BM>
__global__ void __launch_bounds__(256)
spconv_pipe(const float* __restrict__ feat, int ldf,
            const int* __restrict__ nbr,
            const float* __restrict__ W,      // (27, CIN, COUT)
            const float* __restrict__ sb,     // scale[COUT], bias[COUT]
            const float* __restrict__ resid, int ldr,
            const float* __restrict__ red,   int ldred,
            float* __restrict__ out, int ldo, int N)
{
    using C = SpCfg<CIN, COUT, BM>;
    constexpr int CK = C::CK, NCH = C::NCH, SP = C::SP, VR = C::VR;
    constexpr int TN = C::TN, TX = C::TX, TY = C::TY, TM = C::TM, TP = C::TP;

    extern __shared__ float smem[];
    float* sfeat = smem;                           // [2][BM*SP]
    float* sW    = smem + 2 * BM * SP;             // [2][CK*COUT]
    int*   snbr  = (int*)(sW + 2 * CK * COUT);     // [27*BM]
    int*   kmeta = snbr + 27 * BM;                 // khit[27] | klist[27] | kn
    int*   khit  = kmeta;
    int*   klist = kmeta + 27;
    int*   knp   = kmeta + 54;

    const uint32_t sfeat_sa = (uint32_t)__cvta_generic_to_shared(sfeat);
    const uint32_t sW_sa    = (uint32_t)__cvta_generic_to_shared(sW);

    const int tid  = threadIdx.x;
    const int tx   = tid % TX;
    const int ty   = tid / TX;
    const int row0 = blockIdx.x * BM;

    // Stage neighbor indices (coalesced global read)
    for (int e = tid; e < BM * 27; e += 256) {
        int r = e / 27, k = e - r * 27;
        int g = row0 + r;
        snbr[k * BM + r] = (g < N) ? nbr[(size_t)g * 27 + k] : -1;
    }
    __syncthreads();
    if (tid < 27) {
        int h = 0;
        for (int r = 0; r < BM && !h; ++r) h = (snbr[tid * BM + r] >= 0);
        khit[tid] = h;
    }
    __syncthreads();
    if (tid == 0) {
        int n = 0;
        for (int k = 0; k < 27; ++k) if (khit[k]) klist[n++] = k;
        *knp = n;
    }
    __syncthreads();
    const int NS = (*knp) * NCH;

    ull acc[TP][TN];
#pragma unroll
    for (int p = 0; p < TP; ++p)
#pragma unroll
        for (int j = 0; j < TN; ++j) acc[p][j] = 0ull;

    // -------- stage helper (inlined twice) --------
    auto stage = [&](int s) {
        const int k  = klist[s / NCH];
        const int ch = s - (s / NCH) * NCH;
        const int kb = s & 1;
        const uint32_t fb = sfeat_sa + (uint32_t)(kb * BM * SP) * 4u;
        for (int u = tid; u < BM * VR; u += 256) {
            int r = u / VR, v = u - r * VR;
            int idx = snbr[k * BM + r];
            const float* g = feat + (size_t)(idx < 0 ? 0 : idx) * ldf
                           + ch * CK + v * 4;
            cp_async16(fb + (uint32_t)(r * SP + v * 4) * 4u, g, idx < 0 ? 0 : 16);
        }
        const float* wg = W + ((size_t)k * CIN + (size_t)ch * CK) * COUT;
        const uint32_t wb = sW_sa + (uint32_t)(kb * CK * COUT) * 4u;
        for (int u = tid; u < CK * COUT / 4; u += 256)
            cp_async16(wb + (uint32_t)u * 16u, wg + u * 4, 16);
    };

    if (NS > 0) {
        stage(0);
        cp_commit();
        for (int s = 0; s < NS; ++s) {
            if (s + 1 < NS) {
                stage(s + 1);
                cp_commit();
                cp_wait<1>();
            } else {
                cp_wait<0>();
            }
            __syncthreads();

            const float* fb = sfeat + (s & 1) * BM * SP;
            const float* wb = sW    + (s & 1) * CK * COUT;
#pragma unroll 8
            for (int cin = 0; cin < CK; ++cin) {
                float4 wv = *(const float4*)(wb + cin * COUT + tx * TN);
                ull w2[TN];
                w2[0] = pack2(wv.x, wv.x);
                w2[1] = pack2(wv.y, wv.y);
                w2[2] = pack2(wv.z, wv.z);
                w2[3] = pack2(wv.w, wv.w);
                float f[TM];
#pragma unroll
                for (int i = 0; i < TM; ++i)
                    f[i] = fb[(ty + TY * i) * SP + cin];
#pragma unroll
                for (int p = 0; p < TP; ++p) {
                    ull f2 = pack2(f[2 * p], f[2 * p + 1]);
#pragma unroll
                    for (int j = 0; j < TN; ++j)
                        acc[p][j] = ffma2(f2, w2[j], acc[p][j]);
                }
            }
            __syncthreads();
        }
    }

    // -------- epilogue: *scale + bias (+resid) -> relu (+pair-reduce) --------
    float sc[TN], bi[TN];
#pragma unroll
    for (int j = 0; j < TN; ++j) {
        sc[j] = sb[tx * TN + j];
        bi[j] = sb[COUT + tx * TN + j];
    }

#pragma unroll
    for (int p = 0; p < TP; ++p) {
        float v0[TN], v1[TN];
#pragma unroll
        for (int j = 0; j < TN; ++j) unpack2(acc[p][j], v0[j], v1[j]);

#pragma unroll
        for (int half = 0; half < 2; ++half) {
            float* v = half ? v1 : v0;
            int r = row0 + ty + TY * (2 * p + half);
            if (r >= N) continue;
#pragma unroll
            for (int j = 0; j < TN; ++j) v[j] = v[j] * sc[j] + bi[j];
            if (resid) {
                float4 rr = *(const float4*)(resid + (size_t)r * ldr + tx * TN);
                v[0] += rr.x; v[1] += rr.y; v[2] += rr.z; v[3] += rr.w;
            }
#pragma unroll
            for (int j = 0; j < TN; ++j) v[j] = fmaxf(v[j], 0.f);
            if (red) {
                float4 ra = *(const float4*)(red + (size_t)r * ldred + 2 * tx * TN);
                float4 rb = *(const float4*)(red + (size_t)r * ldred + 2 * tx * TN + 4);
                v[0] += ra.x + ra.y; v[1] += ra.z + ra.w;
                v[2] += rb.x + rb.y; v[3] += rb.z + rb.w;
            }
            *(float4*)(out + (size_t)r * ldo + tx * TN) =
                make_float4(v[0], v[1], v[2], v[3]);
        }
    }
}

template <int CIN, int COUT>
static void conv_launch(const float* feat, int ldf, const int* nbr,
                        const float* W, const float* sb,
                        const float* resid, int ldr,
                        const float* red, int ldred,
                        float* out, int ldo, int N)
{
    constexpr int BM = (CIN == 128) ? 64 : 128;
    constexpr int SM = SpCfg<CIN, COUT, BM>::SMEM_BYTES;
    cudaFuncSetAttribute(spconv_pipe<CIN, COUT, BM>,
                         cudaFuncAttributeMaxDynamicSharedMemorySize, SM);
    const int grid = (N + BM - 1) / BM;
    spconv_pipe<CIN, COUT, BM><<<grid, 256, SM>>>(
        feat, ldf, nbr, W, sb, resid, ldr, red, ldred, out, ldo, N);
}

extern "C" void kernel_launch(void* const* d_in, const int* in_sizes, int n_in,
                              void* d_out, int out_size)
{
    const float* voxel  = (const float*)d_in[0];
    const float* Win    = (const float*)d_in[1];
    const float* W32    = (const float*)d_in[2];
    const float* W64    = (const float*)d_in[3];
    const float* Wd3    = (const float*)d_in[4];
    const float* W6432  = (const float*)d_in[5];
    const float* W12864 = (const float*)d_in[6];
    const float* bn32   = (const float*)d_in[7];
    const float* bn64   = (const float*)d_in[8];
    const int* nbr1  = (const int*)d_in[9];
    const int* nbr2  = (const int*)d_in[10];
    const int* nbr3  = (const int*)d_in[11];
    const int* nbr4  = (const int*)d_in[12];
    const int* nbrd2 = (const int*)d_in[13];
    const int* nbrd3 = (const int*)d_in[14];
    const int* nbrd4 = (const int*)d_in[15];
    const int* nbri4 = (const int*)d_in[16];
    const int* nbri3 = (const int*)d_in[17];
    const int* nbri2 = (const int*)d_in[18];

    const int N1 = in_sizes[9]  / 27;
    const int N2 = in_sizes[10] / 27;
    const int N3 = in_sizes[11] / 27;
    const int N4 = in_sizes[12] / 27;

    float* pool = nullptr;
    cudaGetSymbolAddress((void**)&pool, g_pool);

    size_t o = 0;
    auto take = [&](size_t n) { size_t r = o; o += (n + 255) & ~(size_t)255; return r; };
    float* A    = pool + take((size_t)N1 * 32);
    float* X1   = pool + take((size_t)N1 * 32);
    float* cat1 = pool + take((size_t)N1 * 64);
    float* C    = pool + take((size_t)N2 * 32);
    float* Dm   = pool + take((size_t)N2 * 32);
    float* X2   = pool + take((size_t)N2 * 32);
    float* cat2 = pool + take((size_t)N2 * 64);
    float* Fm   = pool + take((size_t)N3 * 64);
    float* G    = pool + take((size_t)N3 * 64);
    float* X3   = pool + take((size_t)N3 * 64);
    float* cat3 = pool + take((size_t)N3 * 128);
    float* I    = pool + take((size_t)N4 * 64);
    float* J    = pool + take((size_t)N4 * 64);
    float* cat4 = pool + take((size_t)N4 * 128);

    float* outp = (float*)d_out;

    const size_t S32   = 27u * 32 * 32;
    const size_t S64   = 27u * 64 * 64;
    const size_t S6432 = 27u * 64 * 32;
    const size_t S1286 = 27u * 128 * 64;

    // ---- Encoder ----
    conv_launch<4, 32>(voxel, 4, nbr1, Win, bn32 + 0 * 64, nullptr, 0, nullptr, 0, A, 32, N1);
    conv_launch<32, 32>(A, 32, nbr1, W32 + 0 * S32, bn32 + 1 * 64, nullptr, 0, nullptr, 0, X1, 32, N1);
    conv_launch<32, 32>(X1, 32, nbrd2, W32 + 1 * S32, bn32 + 2 * 64, nullptr, 0, nullptr, 0, C, 32, N2);
    conv_launch<32, 32>(C, 32, nbr2, W32 + 2 * S32, bn32 + 3 * 64, nullptr, 0, nullptr, 0, Dm, 32, N2);
    conv_launch<32, 32>(Dm, 32, nbr2, W32 + 3 * S32, bn32 + 4 * 64, nullptr, 0, nullptr, 0, X2, 32, N2);
    conv_launch<32, 64>(X2, 32, nbrd3, Wd3, bn64 + 0 * 128, nullptr, 0, nullptr, 0, Fm, 64, N3);
    conv_launch<64, 64>(Fm, 64, nbr3, W64 + 0 * S64, bn64 + 1 * 128, nullptr, 0, nullptr, 0, G, 64, N3);
    conv_launch<64, 64>(G, 64, nbr3, W64 + 1 * S64, bn64 + 2 * 128, nullptr, 0, nullptr, 0, X3, 64, N3);
    conv_launch<64, 64>(X3, 64, nbrd4, W64 + 2 * S64, bn64 + 3 * 128, nullptr, 0, nullptr, 0, I, 64, N4);
    conv_launch<64, 64>(I, 64, nbr4, W64 + 3 * S64, bn64 + 4 * 128, nullptr, 0, nullptr, 0, J, 64, N4);
    conv_launch<64, 64>(J, 64, nbr4, W64 + 4 * S64, bn64 + 5 * 128, nullptr, 0, nullptr, 0, cat4, 128, N4);

    // ---- Bottleneck ----
    conv_launch<64, 64>(cat4, 128, nbr4, W64 + 5 * S64, bn64 + 6 * 128, nullptr, 0, nullptr, 0, I, 64, N4);
    conv_launch<64, 64>(I, 64, nbr4, W64 + 6 * S64, bn64 + 7 * 128, cat4, 128, nullptr, 0, cat4 + 64, 128, N4);
    conv_launch<128, 64>(cat4, 128, nbr4, W12864 + 0 * S1286, bn64 + 11 * 128, nullptr, 0, cat4, 128, J, 64, N4);

    // ---- Decoder level 3 ----
    conv_launch<64, 64>(J, 64, nbri4, W64 + 7 * S64, bn64 + 8 * 128, nullptr, 0, nullptr, 0, cat3, 128, N3);
    conv_launch<64, 64>(X3, 64, nbr3, W64 + 8 * S64, bn64 + 9 * 128, nullptr, 0, nullptr, 0, Fm, 64, N3);
    conv_launch<64, 64>(Fm, 64, nbr3, W64 + 9 * S64, bn64 + 10 * 128, X3, 64, nullptr, 0, cat3 + 64, 128, N3);
    conv_launch<128, 64>(cat3, 128, nbr3, W12864 + 1 * S1286, bn64 + 12 * 128, nullptr, 0, cat3, 128, G, 64, N3);

    // ---- Decoder level 2 ----
    conv_launch<64, 32>(G, 64, nbri3, W6432 + 0 * S6432, bn32 + 11 * 64, nullptr, 0, nullptr, 0, cat2, 64, N2);
    conv_launch<32, 32>(X2, 32, nbr2, W32 + 4 * S32, bn32 + 5 * 64, nullptr, 0, nullptr, 0, C, 32, N2);
    conv_launch<32, 32>(C, 32, nbr2, W32 + 5 * S32, bn32 + 6 * 64, X2, 32, nullptr, 0, cat2 + 32, 64, N2);
    conv_launch<64, 32>(cat2, 64, nbr2, W6432 + 1 * S6432, bn32 + 12 * 64, nullptr, 0, cat2, 64, Dm, 32, N2);

    // ---- Decoder level 1 ----
    conv_launch<32, 32>(Dm, 32, nbri2, W32 + 6 * S32, bn32 + 7 * 64, nullptr, 0, nullptr, 0, cat1, 64, N1);
    conv_launch<32, 32>(X1, 32, nbr1, W32 + 7 * S32, bn32 + 8 * 64, nullptr, 0, nullptr, 0, A, 32, N1);
    conv_launch<32, 32>(A, 32, nbr1, W32 + 8 * S32, bn32 + 9 * 64, X1, 32, nullptr, 0, cat1 + 32, 64, N1);
    conv_launch<64, 32>(cat1, 64, nbr1, W6432 + 2 * S6432, bn32 + 13 * 64, nullptr, 0, cat1, 64, A, 32, N1);

    // ---- Head ----
    conv_launch<32, 32>(A, 32, nbr1, W32 + 9 * S32, bn32 + 10 * 64, nullptr, 0, nullptr, 0, outp, 32, N1);
}

// round 5
// speedup vs baseline: 3.4437x; 2.5382x over previous
#include <cuda_runtime.h>
#include <cstddef>
#include <cstdint>

// ---------------------------------------------------------------------------
// Sparse 3D UNet forward.  cp.async double-buffered sparse-conv GEMM with
// tf32 tensor-core mma.sync.m16n8k8.
//   out[i, cout] = epi( sum_k sum_cin feat[nbr[i,k], cin] * W[k,cin,cout] )
// ---------------------------------------------------------------------------

__device__ float g_pool[96u * 1024u * 1024u];   // 384 MB scratch (static: legal)

__device__ __forceinline__ void cp_async16(uint32_t dst, const void* src, int nbytes) {
    asm volatile("cp.async.cg.shared.global [%0], [%1], 16, %2;"
                 :: "r"(dst), "l"(src), "r"(nbytes));
}
__device__ __forceinline__ void cp_commit() {
    asm volatile("cp.async.commit_group;");
}
template <int NG> __device__ __forceinline__ void cp_wait() {
    asm volatile("cp.async.wait_group %0;" :: "n"(NG));
}
__device__ __forceinline__ uint32_t tf32(float x) {
    uint32_t r; asm("cvt.rna.tf32.f32 %0, %1;" : "=r"(r) : "f"(x)); return r;
}
__device__ __forceinline__ void mma_tf32(float c[4], uint32_t a0, uint32_t a1,
                                         uint32_t a2, uint32_t a3,
                                         uint32_t b0, uint32_t b1) {
    asm volatile(
        "mma.sync.aligned.m16n8k8.row.col.f32.tf32.tf32.f32 "
        "{%0,%1,%2,%3},{%4,%5,%6,%7},{%8,%9},{%0,%1,%2,%3};"
        : "+f"(c[0]), "+f"(c[1]), "+f"(c[2]), "+f"(c[3])
        : "r"(a0), "r"(a1), "r"(a2), "r"(a3), "r"(b0), "r"(b1));
}

template <int CIN, int COUT>
struct SpCfg {
    static constexpr int BM  = 128;
    static constexpr int CK  = (CIN < 32) ? CIN : 32;   // channel chunk
    static constexpr int CK8 = (CK < 8) ? 8 : CK;       // padded K (mma k8)
    static constexpr int NCH = CIN / CK;
    static constexpr int SP  = CK8 + 4;                 // feat row stride
    static constexpr int SPW = COUT + 8;                // W row stride
    static constexpr int VR  = CK / 4;                  // 16B vecs per feat row
    static constexpr int NT  = COUT / 8;                // n-tiles per warp
    static constexpr int KS  = CK8 / 8;                 // k8 steps per stage
    static constexpr int SMEM_BYTES =
        (2 * BM * SP + 2 * CK8 * SPW) * 4 + 27 * BM * 4 + 64 * 4;
};

template <int CIN, int COUT>
__global__ void __launch_bounds__(256)
spconv_mma(const float* __restrict__ feat, int ldf,
           const int* __restrict__ nbr,
           const float* __restrict__ W,      // (27, CIN, COUT)
           const float* __restrict__ sb,     // scale[COUT], bias[COUT]
           const float* __restrict__ resid, int ldr,
           const float* __restrict__ red,   int ldred,
           float* __restrict__ out, int ldo, int N)
{
    using C = SpCfg<CIN, COUT>;
    constexpr int BM = C::BM, CK = C::CK, CK8 = C::CK8, NCH = C::NCH;
    constexpr int SP = C::SP, SPW = C::SPW, VR = C::VR, NT = C::NT, KS = C::KS;

    extern __shared__ float smem[];
    float* sfeat = smem;                              // [2][BM*SP]
    float* sW    = smem + 2 * BM * SP;                // [2][CK8*SPW]
    int*   snbr  = (int*)(sW + 2 * CK8 * SPW);        // [27*BM]
    int*   kmeta = snbr + 27 * BM;
    int*   khit  = kmeta;
    int*   klist = kmeta + 27;
    int*   knp   = kmeta + 54;

    const uint32_t sfeat_sa = (uint32_t)__cvta_generic_to_shared(sfeat);
    const uint32_t sW_sa    = (uint32_t)__cvta_generic_to_shared(sW);

    const int tid  = threadIdx.x;
    const int lane = tid & 31;
    const int wid  = tid >> 5;             // 8 warps
    const int row0 = blockIdx.x * BM;

    // Zero pad regions once when K is padded (CIN=4 layer)
    if (CK8 != CK) {
        for (int u = tid; u < 2 * BM * SP + 2 * CK8 * SPW; u += 256) smem[u] = 0.f;
    }

    // Stage neighbor indices
    for (int e = tid; e < BM * 27; e += 256) {
        int r = e / 27, k = e - r * 27;
        int g = row0 + r;
        snbr[k * BM + r] = (g < N) ? nbr[(size_t)g * 27 + k] : -1;
    }
    __syncthreads();
    if (tid < 27) {
        int h = 0;
        for (int r = 0; r < BM && !h; ++r) h = (snbr[tid * BM + r] >= 0);
        khit[tid] = h;
    }
    __syncthreads();
    if (tid == 0) {
        int n = 0;
        for (int k = 0; k < 27; ++k) if (khit[k]) klist[n++] = k;
        *knp = n;
    }
    __syncthreads();
    const int NS = (*knp) * NCH;

    float acc[NT][4];
#pragma unroll
    for (int t = 0; t < NT; ++t)
#pragma unroll
        for (int j = 0; j < 4; ++j) acc[t][j] = 0.f;

    auto stage = [&](int s) {
        const int k  = klist[s / NCH];
        const int ch = s - (s / NCH) * NCH;
        const int kb = s & 1;
        const uint32_t fb = sfeat_sa + (uint32_t)(kb * BM * SP) * 4u;
        for (int u = tid; u < BM * VR; u += 256) {
            int r = u / VR, v = u - r * VR;
            int idx = snbr[k * BM + r];
            const float* g = feat + (size_t)(idx < 0 ? 0 : idx) * ldf
                           + ch * CK + v * 4;
            cp_async16(fb + (uint32_t)(r * SP + v * 4) * 4u, g, idx < 0 ? 0 : 16);
        }
        const float* wg = W + ((size_t)k * CIN + (size_t)ch * CK) * COUT;
        const uint32_t wb = sW_sa + (uint32_t)(kb * CK8 * SPW) * 4u;
        for (int u = tid; u < CK * COUT / 4; u += 256) {
            int c = u / (COUT / 4), v = u - c * (COUT / 4);
            cp_async16(wb + (uint32_t)(c * SPW + v * 4) * 4u, wg + c * COUT + v * 4, 16);
        }
    };

    const int mrow = wid * 16 + (lane >> 2);   // A-frag row within tile
    const int kq   = lane & 3;                  // A col / B k quad
    const int nq   = lane >> 2;                 // B n index

    if (NS > 0) {
        stage(0);
        cp_commit();
        for (int s = 0; s < NS; ++s) {
            if (s + 1 < NS) { stage(s + 1); cp_commit(); cp_wait<1>(); }
            else           { cp_wait<0>(); }
            __syncthreads();

            const float* fb = sfeat + (s & 1) * BM * SP;
            const float* wb = sW    + (s & 1) * CK8 * SPW;
#pragma unroll
            for (int k8 = 0; k8 < KS; ++k8) {
                const int kc = k8 * 8;
                const float* fr0 = fb + mrow * SP + kc + kq;
                const float* fr1 = fr0 + 8 * SP;
                uint32_t a0 = tf32(fr0[0]);
                uint32_t a1 = tf32(fr1[0]);
                uint32_t a2 = tf32(fr0[4]);
                uint32_t a3 = tf32(fr1[4]);
                const float* wr0 = wb + (kc + kq) * SPW + nq;
                const float* wr1 = wr0 + 4 * SPW;
#pragma unroll
                for (int t = 0; t < NT; ++t) {
                    uint32_t b0 = tf32(wr0[t * 8]);
                    uint32_t b1 = tf32(wr1[t * 8]);
                    mma_tf32(acc[t], a0, a1, a2, a3, b0, b1);
                }
            }
            __syncthreads();
        }
    }

    // -------- epilogue --------
    // thread holds cols (col0, col0+1) at rows (r0, r0+8) per n-tile
    const int r0 = row0 + mrow;
#pragma unroll
    for (int t = 0; t < NT; ++t) {
        const int col = t * 8 + 2 * kq;
        const float s0 = sb[col],        s1 = sb[col + 1];
        const float b0 = sb[COUT + col], b1 = sb[COUT + col + 1];
#pragma unroll
        for (int h = 0; h < 2; ++h) {
            const int r = r0 + 8 * h;
            if (r >= N) continue;
            float v0 = acc[t][2 * h]     * s0 + b0;
            float v1 = acc[t][2 * h + 1] * s1 + b1;
            if (resid) {
                float2 rr = *(const float2*)(resid + (size_t)r * ldr + col);
                v0 += rr.x; v1 += rr.y;
            }
            v0 = fmaxf(v0, 0.f);
            v1 = fmaxf(v1, 0.f);
            if (red) {
                float4 ra = *(const float4*)(red + (size_t)r * ldred + 2 * col);
                v0 += ra.x + ra.y;
                v1 += ra.z + ra.w;
            }
            *(float2*)(out + (size_t)r * ldo + col) = make_float2(v0, v1);
        }
    }
}

template <int CIN, int COUT>
static void conv_launch(const float* feat, int ldf, const int* nbr,
                        const float* W, const float* sb,
                        const float* resid, int ldr,
                        const float* red, int ldred,
                        float* out, int ldo, int N)
{
    constexpr int SM = SpCfg<CIN, COUT>::SMEM_BYTES;
    cudaFuncSetAttribute(spconv_mma<CIN, COUT>,
                         cudaFuncAttributeMaxDynamicSharedMemorySize, SM);
    const int grid = (N + 127) / 128;
    spconv_mma<CIN, COUT><<<grid, 256, SM>>>(
        feat, ldf, nbr, W, sb, resid, ldr, red, ldred, out, ldo, N);
}

extern "C" void kernel_launch(void* const* d_in, const int* in_sizes, int n_in,
                              void* d_out, int out_size)
{
    const float* voxel  = (const float*)d_in[0];
    const float* Win    = (const float*)d_in[1];
    const float* W32    = (const float*)d_in[2];
    const float* W64    = (const float*)d_in[3];
    const float* Wd3    = (const float*)d_in[4];
    const float* W6432  = (const float*)d_in[5];
    const float* W12864 = (const float*)d_in[6];
    const float* bn32   = (const float*)d_in[7];
    const float* bn64   = (const float*)d_in[8];
    const int* nbr1  = (const int*)d_in[9];
    const int* nbr2  = (const int*)d_in[10];
    const int* nbr3  = (const int*)d_in[11];
    const int* nbr4  = (const int*)d_in[12];
    const int* nbrd2 = (const int*)d_in[13];
    const int* nbrd3 = (const int*)d_in[14];
    const int* nbrd4 = (const int*)d_in[15];
    const int* nbri4 = (const int*)d_in[16];
    const int* nbri3 = (const int*)d_in[17];
    const int* nbri2 = (const int*)d_in[18];

    const int N1 = in_sizes[9]  / 27;
    const int N2 = in_sizes[10] / 27;
    const int N3 = in_sizes[11] / 27;
    const int N4 = in_sizes[12] / 27;

    float* pool = nullptr;
    cudaGetSymbolAddress((void**)&pool, g_pool);

    size_t o = 0;
    auto take = [&](size_t n) { size_t r = o; o += (n + 255) & ~(size_t)255; return r; };
    float* A    = pool + take((size_t)N1 * 32);
    float* X1   = pool + take((size_t)N1 * 32);
    float* cat1 = pool + take((size_t)N1 * 64);
    float* C    = pool + take((size_t)N2 * 32);
    float* Dm   = pool + take((size_t)N2 * 32);
    float* X2   = pool + take((size_t)N2 * 32);
    float* cat2 = pool + take((size_t)N2 * 64);
    float* Fm   = pool + take((size_t)N3 * 64);
    float* G    = pool + take((size_t)N3 * 64);
    float* X3   = pool + take((size_t)N3 * 64);
    float* cat3 = pool + take((size_t)N3 * 128);
    float* I    = pool + take((size_t)N4 * 64);
    float* J    = pool + take((size_t)N4 * 64);
    float* cat4 = pool + take((size_t)N4 * 128);

    float* outp = (float*)d_out;

    const size_t S32   = 27u * 32 * 32;
    const size_t S64   = 27u * 64 * 64;
    const size_t S6432 = 27u * 64 * 32;
    const size_t S1286 = 27u * 128 * 64;

    // ---- Encoder ----
    conv_launch<4, 32>(voxel, 4, nbr1, Win, bn32 + 0 * 64, nullptr, 0, nullptr, 0, A, 32, N1);
    conv_launch<32, 32>(A, 32, nbr1, W32 + 0 * S32, bn32 + 1 * 64, nullptr, 0, nullptr, 0, X1, 32, N1);
    conv_launch<32, 32>(X1, 32, nbrd2, W32 + 1 * S32, bn32 + 2 * 64, nullptr, 0, nullptr, 0, C, 32, N2);
    conv_launch<32, 32>(C, 32, nbr2, W32 + 2 * S32, bn32 + 3 * 64, nullptr, 0, nullptr, 0, Dm, 32, N2);
    conv_launch<32, 32>(Dm, 32, nbr2, W32 + 3 * S32, bn32 + 4 * 64, nullptr, 0, nullptr, 0, X2, 32, N2);
    conv_launch<32, 64>(X2, 32, nbrd3, Wd3, bn64 + 0 * 128, nullptr, 0, nullptr, 0, Fm, 64, N3);
    conv_launch<64, 64>(Fm, 64, nbr3, W64 + 0 * S64, bn64 + 1 * 128, nullptr, 0, nullptr, 0, G, 64, N3);
    conv_launch<64, 64>(G, 64, nbr3, W64 + 1 * S64, bn64 + 2 * 128, nullptr, 0, nullptr, 0, X3, 64, N3);
    conv_launch<64, 64>(X3, 64, nbrd4, W64 + 2 * S64, bn64 + 3 * 128, nullptr, 0, nullptr, 0, I, 64, N4);
    conv_launch<64, 64>(I, 64, nbr4, W64 + 3 * S64, bn64 + 4 * 128, nullptr, 0, nullptr, 0, J, 64, N4);
    conv_launch<64, 64>(J, 64, nbr4, W64 + 4 * S64, bn64 + 5 * 128, nullptr, 0, nullptr, 0, cat4, 128, N4);

    // ---- Bottleneck ----
    conv_launch<64, 64>(cat4, 128, nbr4, W64 + 5 * S64, bn64 + 6 * 128, nullptr, 0, nullptr, 0, I, 64, N4);
    conv_launch<64, 64>(I, 64, nbr4, W64 + 6 * S64, bn64 + 7 * 128, cat4, 128, nullptr, 0, cat4 + 64, 128, N4);
    conv_launch<128, 64>(cat4, 128, nbr4, W12864 + 0 * S1286, bn64 + 11 * 128, nullptr, 0, cat4, 128, J, 64, N4);

    // ---- Decoder level 3 ----
    conv_launch<64, 64>(J, 64, nbri4, W64 + 7 * S64, bn64 + 8 * 128, nullptr, 0, nullptr, 0, cat3, 128, N3);
    conv_launch<64, 64>(X3, 64, nbr3, W64 + 8 * S64, bn64 + 9 * 128, nullptr, 0, nullptr, 0, Fm, 64, N3);
    conv_launch<64, 64>(Fm, 64, nbr3, W64 + 9 * S64, bn64 + 10 * 128, X3, 64, nullptr, 0, cat3 + 64, 128, N3);
    conv_launch<128, 64>(cat3, 128, nbr3, W12864 + 1 * S1286, bn64 + 12 * 128, nullptr, 0, cat3, 128, G, 64, N3);

    // ---- Decoder level 2 ----
    conv_launch<64, 32>(G, 64, nbri3, W6432 + 0 * S6432, bn32 + 11 * 64, nullptr, 0, nullptr, 0, cat2, 64, N2);
    conv_launch<32, 32>(X2, 32, nbr2, W32 + 4 * S32, bn32 + 5 * 64, nullptr, 0, nullptr, 0, C, 32, N2);
    conv_launch<32, 32>(C, 32, nbr2, W32 + 5 * S32, bn32 + 6 * 64, X2, 32, nullptr, 0, cat2 + 32, 64, N2);
    conv_launch<64, 32>(cat2, 64, nbr2, W6432 + 1 * S6432, bn32 + 12 * 64, nullptr, 0, cat2, 64, Dm, 32, N2);

    // ---- Decoder level 1 ----
    conv_launch<32, 32>(Dm, 32, nbri2, W32 + 6 * S32, bn32 + 7 * 64, nullptr, 0, nullptr, 0, cat1, 64, N1);
    conv_launch<32, 32>(X1, 32, nbr1, W32 + 7 * S32, bn32 + 8 * 64, nullptr, 0, nullptr, 0, A, 32, N1);
    conv_launch<32, 32>(A, 32, nbr1, W32 + 8 * S32, bn32 + 9 * 64, X1, 32, nullptr, 0, cat1 + 32, 64, N1);
    conv_launch<64, 32>(cat1, 64, nbr1, W6432 + 2 * S6432, bn32 + 13 * 64, nullptr, 0, cat1, 64, A, 32, N1);

    // ---- Head ----
    conv_launch<32, 32>(A, 32, nbr1, W32 + 9 * S32, bn32 + 10 * 64, nullptr, 0, nullptr, 0, outp, 32, N1);
}

// round 7
// speedup vs baseline: 3.7345x; 1.0844x over previous
#include <cuda_runtime.h>
#include <cstddef>
#include <cstdint>

// ---------------------------------------------------------------------------
// Sparse 3D UNet forward.  cp.async double-buffered sparse-conv GEMM with
// tf32 tensor-core mma.sync.m16n8k8.  All tf32 conversion hoisted out of the
// inner loop: weights preconverted once per launch, feature maps carry a
// tf32 shadow written by the producing epilogue.
// Pool enlarged to 224M floats (896 MB): fp32 + shadow copies of every
// feature map plus tf32 weight copies must fit (R6 failed on pool overflow).
// ---------------------------------------------------------------------------

__device__ float g_pool[224u * 1024u * 1024u];   // 896 MB scratch (static: legal)

__device__ __forceinline__ void cp_async16(uint32_t dst, const void* src, int nbytes) {
    asm volatile("cp.async.cg.shared.global [%0], [%1], 16, %2;"
                 :: "r"(dst), "l"(src), "r"(nbytes));
}
__device__ __forceinline__ void cp_commit() {
    asm volatile("cp.async.commit_group;");
}
template <int NG> __device__ __forceinline__ void cp_wait() {
    asm volatile("cp.async.wait_group %0;" :: "n"(NG));
}
__device__ __forceinline__ uint32_t tf32(float x) {
    uint32_t r; asm("cvt.rna.tf32.f32 %0, %1;" : "=r"(r) : "f"(x)); return r;
}
__device__ __forceinline__ void mma_tf32(float c[4], uint32_t a0, uint32_t a1,
                                         uint32_t a2, uint32_t a3,
                                         uint32_t b0, uint32_t b1) {
    asm volatile(
        "mma.sync.aligned.m16n8k8.row.col.f32.tf32.tf32.f32 "
        "{%0,%1,%2,%3},{%4,%5,%6,%7},{%8,%9},{%0,%1,%2,%3};"
        : "+f"(c[0]), "+f"(c[1]), "+f"(c[2]), "+f"(c[3])
        : "r"(a0), "r"(a1), "r"(a2), "r"(a3), "r"(b0), "r"(b1));
}

// Convert fp32 -> tf32-rounded fp32 bits (grid-stride).
__global__ void cvt_tf32_kernel(const float* __restrict__ in,
                                float* __restrict__ out, int n) {
    for (int i = blockIdx.x * blockDim.x + threadIdx.x; i < n;
         i += gridDim.x * blockDim.x)
        out[i] = __uint_as_float(tf32(in[i]));
}

template <int CIN, int COUT>
struct SpCfg {
    static constexpr int BM  = 128;
    static constexpr int CK  = (CIN < 32) ? CIN : 32;   // channel chunk
    static constexpr int CK8 = (CK < 8) ? 8 : CK;       // padded K (mma k8)
    static constexpr int NCH = CIN / CK;
    static constexpr int SP  = CK8 + 4;                 // feat row stride
    static constexpr int SPW = COUT + 8;                // W row stride
    static constexpr int VR  = CK / 4;                  // 16B vecs per feat row
    static constexpr int NT  = COUT / 8;                // n-tiles per warp
    static constexpr int KS  = CK8 / 8;                 // k8 steps per stage
    static constexpr int SMEM_BYTES =
        (2 * BM * SP + 2 * CK8 * SPW) * 4 + 27 * BM * 4 + 64 * 4;
};

template <int CIN, int COUT>
__global__ void __launch_bounds__(256)
spconv_mma(const float* __restrict__ feat, int ldf,   // tf32-shadow input
           const int* __restrict__ nbr,
           const float* __restrict__ W,      // (27, CIN, COUT), tf32 bits
           const float* __restrict__ sb,     // scale[COUT], bias[COUT]
           const float* __restrict__ resid, int ldr,  // fp32
           const float* __restrict__ red,   int ldred, // fp32
           float* __restrict__ out, int ldo,           // fp32 out
           float* __restrict__ outs,                   // tf32 shadow out (or null)
           int N)
{
    using C = SpCfg<CIN, COUT>;
    constexpr int BM = C::BM, CK = C::CK, CK8 = C::CK8, NCH = C::NCH;
    constexpr int SP = C::SP, SPW = C::SPW, VR = C::VR, NT = C::NT, KS = C::KS;

    extern __shared__ float smem[];
    float* sfeat = smem;                              // [2][BM*SP]
    float* sW    = smem + 2 * BM * SP;                // [2][CK8*SPW]
    int*   snbr  = (int*)(sW + 2 * CK8 * SPW);        // [27*BM]
    int*   kmeta = snbr + 27 * BM;
    int*   khit  = kmeta;
    int*   klist = kmeta + 27;
    int*   knp   = kmeta + 54;

    const uint32_t sfeat_sa = (uint32_t)__cvta_generic_to_shared(sfeat);
    const uint32_t sW_sa    = (uint32_t)__cvta_generic_to_shared(sW);

    const int tid  = threadIdx.x;
    const int lane = tid & 31;
    const int wid  = tid >> 5;             // 8 warps
    const int row0 = blockIdx.x * BM;

    // Zero pad regions once when K is padded (CIN=4 layer)
    if (CK8 != CK) {
        for (int u = tid; u < 2 * BM * SP + 2 * CK8 * SPW; u += 256) smem[u] = 0.f;
    }

    // Stage neighbor indices
    for (int e = tid; e < BM * 27; e += 256) {
        int r = e / 27, k = e - r * 27;
        int g = row0 + r;
        snbr[k * BM + r] = (g < N) ? nbr[(size_t)g * 27 + k] : -1;
    }
    __syncthreads();
    if (tid < 27) {
        int h = 0;
        for (int r = 0; r < BM && !h; ++r) h = (snbr[tid * BM + r] >= 0);
        khit[tid] = h;
    }
    __syncthreads();
    if (tid == 0) {
        int n = 0;
        for (int k = 0; k < 27; ++k) if (khit[k]) klist[n++] = k;
        *knp = n;
    }
    __syncthreads();
    const int NS = (*knp) * NCH;

    float acc[NT][4];
#pragma unroll
    for (int t = 0; t < NT; ++t)
#pragma unroll
        for (int j = 0; j < 4; ++j) acc[t][j] = 0.f;

    auto stage = [&](int s) {
        const int k  = klist[s / NCH];
        const int ch = s - (s / NCH) * NCH;
        const int kb = s & 1;
        const uint32_t fb = sfeat_sa + (uint32_t)(kb * BM * SP) * 4u;
        for (int u = tid; u < BM * VR; u += 256) {
            int r = u / VR, v = u - r * VR;
            int idx = snbr[k * BM + r];
            const float* g = feat + (size_t)(idx < 0 ? 0 : idx) * ldf
                           + ch * CK + v * 4;
            cp_async16(fb + (uint32_t)(r * SP + v * 4) * 4u, g, idx < 0 ? 0 : 16);
        }
        const float* wg = W + ((size_t)k * CIN + (size_t)ch * CK) * COUT;
        const uint32_t wb = sW_sa + (uint32_t)(kb * CK8 * SPW) * 4u;
        for (int u = tid; u < CK * COUT / 4; u += 256) {
            int c = u / (COUT / 4), v = u - c * (COUT / 4);
            cp_async16(wb + (uint32_t)(c * SPW + v * 4) * 4u, wg + c * COUT + v * 4, 16);
        }
    };

    const int mrow = wid * 16 + (lane >> 2);   // A-frag row within tile
    const int kq   = lane & 3;                  // A col / B k quad
    const int nq   = lane >> 2;                 // B n index

    if (NS > 0) {
        stage(0);
        cp_commit();
        for (int s = 0; s < NS; ++s) {
            if (s + 1 < NS) { stage(s + 1); cp_commit(); cp_wait<1>(); }
            else           { cp_wait<0>(); }
            __syncthreads();

            const float* fb = sfeat + (s & 1) * BM * SP;
            const float* wb = sW    + (s & 1) * CK8 * SPW;
#pragma unroll
            for (int k8 = 0; k8 < KS; ++k8) {
                const int kc = k8 * 8;
                const float* fr0 = fb + mrow * SP + kc + kq;
                const float* fr1 = fr0 + 8 * SP;
                uint32_t a0 = __float_as_uint(fr0[0]);
                uint32_t a1 = __float_as_uint(fr1[0]);
                uint32_t a2 = __float_as_uint(fr0[4]);
                uint32_t a3 = __float_as_uint(fr1[4]);
                const float* wr0 = wb + (kc + kq) * SPW + nq;
                const float* wr1 = wr0 + 4 * SPW;
#pragma unroll
                for (int t = 0; t < NT; ++t) {
                    uint32_t b0 = __float_as_uint(wr0[t * 8]);
                    uint32_t b1 = __float_as_uint(wr1[t * 8]);
                    mma_tf32(acc[t], a0, a1, a2, a3, b0, b1);
                }
            }
            __syncthreads();
        }
    }

    // -------- epilogue --------
    const int r0 = row0 + mrow;
#pragma unroll
    for (int t = 0; t < NT; ++t) {
        const int col = t * 8 + 2 * kq;
        const float s0 = sb[col],        s1 = sb[col + 1];
        const float b0 = sb[COUT + col], b1 = sb[COUT + col + 1];
#pragma unroll
        for (int h = 0; h < 2; ++h) {
            const int r = r0 + 8 * h;
            if (r >= N) continue;
            float v0 = acc[t][2 * h]     * s0 + b0;
            float v1 = acc[t][2 * h + 1] * s1 + b1;
            if (resid) {
                float2 rr = *(const float2*)(resid + (size_t)r * ldr + col);
                v0 += rr.x; v1 += rr.y;
            }
            v0 = fmaxf(v0, 0.f);
            v1 = fmaxf(v1, 0.f);
            if (red) {
                float4 ra = *(const float4*)(red + (size_t)r * ldred + 2 * col);
                v0 += ra.x + ra.y;
                v1 += ra.z + ra.w;
            }
            *(float2*)(out + (size_t)r * ldo + col) = make_float2(v0, v1);
            if (outs)
                *(float2*)(outs + (size_t)r * ldo + col) =
                    make_float2(__uint_as_float(tf32(v0)), __uint_as_float(tf32(v1)));
        }
    }
}

template <int CIN, int COUT>
static void conv_launch(const float* feat, int ldf, const int* nbr,
                        const float* W, const float* sb,
                        const float* resid, int ldr,
                        const float* red, int ldred,
                        float* out, int ldo, float* outs, int N)
{
    constexpr int SM = SpCfg<CIN, COUT>::SMEM_BYTES;
    cudaFuncSetAttribute(spconv_mma<CIN, COUT>,
                         cudaFuncAttributeMaxDynamicSharedMemorySize, SM);
    const int grid = (N + 127) / 128;
    spconv_mma<CIN, COUT><<<grid, 256, SM>>>(
        feat, ldf, nbr, W, sb, resid, ldr, red, ldred, out, ldo, outs, N);
}

extern "C" void kernel_launch(void* const* d_in, const int* in_sizes, int n_in,
                              void* d_out, int out_size)
{
    const float* voxel  = (const float*)d_in[0];
    const float* Win    = (const float*)d_in[1];
    const float* W32    = (const float*)d_in[2];
    const float* W64    = (const float*)d_in[3];
    const float* Wd3    = (const float*)d_in[4];
    const float* W6432  = (const float*)d_in[5];
    const float* W12864 = (const float*)d_in[6];
    const float* bn32   = (const float*)d_in[7];
    const float* bn64   = (const float*)d_in[8];
    const int* nbr1  = (const int*)d_in[9];
    const int* nbr2  = (const int*)d_in[10];
    const int* nbr3  = (const int*)d_in[11];
    const int* nbr4  = (const int*)d_in[12];
    const int* nbrd2 = (const int*)d_in[13];
    const int* nbrd3 = (const int*)d_in[14];
    const int* nbrd4 = (const int*)d_in[15];
    const int* nbri4 = (const int*)d_in[16];
    const int* nbri3 = (const int*)d_in[17];
    const int* nbri2 = (const int*)d_in[18];

    const int N1 = in_sizes[9]  / 27;
    const int N2 = in_sizes[10] / 27;
    const int N3 = in_sizes[11] / 27;
    const int N4 = in_sizes[12] / 27;

    float* pool = nullptr;
    cudaGetSymbolAddress((void**)&pool, g_pool);

    size_t o = 0;
    auto take = [&](size_t n) { size_t r = o; o += (n + 255) & ~(size_t)255; return r; };

    // ---- tf32 weight copies ----
    const int nWin    = 27 * 4 * 32;
    const int nW32    = 10 * 27 * 32 * 32;
    const int nW64    = 10 * 27 * 64 * 64;
    const int nWd3    = 27 * 32 * 64;
    const int nW6432  = 3 * 27 * 64 * 32;
    const int nW12864 = 2 * 27 * 128 * 64;
    float* cWin    = pool + take(nWin);
    float* cW32    = pool + take(nW32);
    float* cW64    = pool + take(nW64);
    float* cWd3    = pool + take(nWd3);
    float* cW6432  = pool + take(nW6432);
    float* cW12864 = pool + take(nW12864);
    float* voxs    = pool + take((size_t)N1 * 4);

    // ---- feature buffers: fp32 + tf32 shadow (suffix s) ----
    auto buf2 = [&](size_t n, float*& b, float*& s) {
        b = pool + take(n); s = pool + take(n);
    };
    float *A, *As, *X1, *X1s, *cat1, *cat1s;
    float *C, *Cs, *Dm, *Dms, *X2, *X2s, *cat2, *cat2s;
    float *Fm, *Fms, *G, *Gs, *X3, *X3s, *cat3, *cat3s;
    float *I, *Is, *J, *Js, *cat4, *cat4s;
    buf2((size_t)N1 * 32, A, As);
    buf2((size_t)N1 * 32, X1, X1s);
    buf2((size_t)N1 * 64, cat1, cat1s);
    buf2((size_t)N2 * 32, C, Cs);
    buf2((size_t)N2 * 32, Dm, Dms);
    buf2((size_t)N2 * 32, X2, X2s);
    buf2((size_t)N2 * 64, cat2, cat2s);
    buf2((size_t)N3 * 64, Fm, Fms);
    buf2((size_t)N3 * 64, G, Gs);
    buf2((size_t)N3 * 64, X3, X3s);
    buf2((size_t)N3 * 128, cat3, cat3s);
    buf2((size_t)N4 * 64, I, Is);
    buf2((size_t)N4 * 64, J, Js);
    buf2((size_t)N4 * 128, cat4, cat4s);

    float* outp = (float*)d_out;

    // ---- prologue: convert weights + voxel to tf32 ----
    auto cvt = [&](const float* in, float* out, int n) {
        cvt_tf32_kernel<<<(n + 255) / 256, 256>>>(in, out, n);
    };
    cvt(Win, cWin, nWin);
    cvt(W32, cW32, nW32);
    cvt(W64, cW64, nW64);
    cvt(Wd3, cWd3, nWd3);
    cvt(W6432, cW6432, nW6432);
    cvt(W12864, cW12864, nW12864);
    cvt(voxel, voxs, N1 * 4);

    const size_t S32   = 27u * 32 * 32;
    const size_t S64   = 27u * 64 * 64;
    const size_t S6432 = 27u * 64 * 32;
    const size_t S1286 = 27u * 128 * 64;

    // ---- Encoder ----
    conv_launch<4, 32>(voxs, 4, nbr1, cWin, bn32 + 0 * 64, nullptr, 0, nullptr, 0, A, 32, As, N1);
    conv_launch<32, 32>(As, 32, nbr1, cW32 + 0 * S32, bn32 + 1 * 64, nullptr, 0, nullptr, 0, X1, 32, X1s, N1);
    conv_launch<32, 32>(X1s, 32, nbrd2, cW32 + 1 * S32, bn32 + 2 * 64, nullptr, 0, nullptr, 0, C, 32, Cs, N2);
    conv_launch<32, 32>(Cs, 32, nbr2, cW32 + 2 * S32, bn32 + 3 * 64, nullptr, 0, nullptr, 0, Dm, 32, Dms, N2);
    conv_launch<32, 32>(Dms, 32, nbr2, cW32 + 3 * S32, bn32 + 4 * 64, nullptr, 0, nullptr, 0, X2, 32, X2s, N2);
    conv_launch<32, 64>(X2s, 32, nbrd3, cWd3, bn64 + 0 * 128, nullptr, 0, nullptr, 0, Fm, 64, Fms, N3);
    conv_launch<64, 64>(Fms, 64, nbr3, cW64 + 0 * S64, bn64 + 1 * 128, nullptr, 0, nullptr, 0, G, 64, Gs, N3);
    conv_launch<64, 64>(Gs, 64, nbr3, cW64 + 1 * S64, bn64 + 2 * 128, nullptr, 0, nullptr, 0, X3, 64, X3s, N3);
    conv_launch<64, 64>(X3s, 64, nbrd4, cW64 + 2 * S64, bn64 + 3 * 128, nullptr, 0, nullptr, 0, I, 64, Is, N4);
    conv_launch<64, 64>(Is, 64, nbr4, cW64 + 3 * S64, bn64 + 4 * 128, nullptr, 0, nullptr, 0, J, 64, Js, N4);
    conv_launch<64, 64>(Js, 64, nbr4, cW64 + 4 * S64, bn64 + 5 * 128, nullptr, 0, nullptr, 0, cat4, 128, cat4s, N4);

    // ---- Bottleneck ----
    conv_launch<64, 64>(cat4s, 128, nbr4, cW64 + 5 * S64, bn64 + 6 * 128, nullptr, 0, nullptr, 0, I, 64, Is, N4);
    conv_launch<64, 64>(Is, 64, nbr4, cW64 + 6 * S64, bn64 + 7 * 128, cat4, 128, nullptr, 0, cat4 + 64, 128, cat4s + 64, N4);
    conv_launch<128, 64>(cat4s, 128, nbr4, cW12864 + 0 * S1286, bn64 + 11 * 128, nullptr, 0, cat4, 128, J, 64, Js, N4);

    // ---- Decoder level 3 ----
    conv_launch<64, 64>(Js, 64, nbri4, cW64 + 7 * S64, bn64 + 8 * 128, nullptr, 0, nullptr, 0, cat3, 128, cat3s, N3);
    conv_launch<64, 64>(X3s, 64, nbr3, cW64 + 8 * S64, bn64 + 9 * 128, nullptr, 0, nullptr, 0, Fm, 64, Fms, N3);
    conv_launch<64, 64>(Fms, 64, nbr3, cW64 + 9 * S64, bn64 + 10 * 128, X3, 64, nullptr, 0, cat3 + 64, 128, cat3s + 64, N3);
    conv_launch<128, 64>(cat3s, 128, nbr3, cW12864 + 1 * S1286, bn64 + 12 * 128, nullptr, 0, cat3, 128, G, 64, Gs, N3);

    // ---- Decoder level 2 ----
    conv_launch<64, 32>(Gs, 64, nbri3, cW6432 + 0 * S6432, bn32 + 11 * 64, nullptr, 0, nullptr, 0, cat2, 64, cat2s, N2);
    conv_launch<32, 32>(X2s, 32, nbr2, cW32 + 4 * S32, bn32 + 5 * 64, nullptr, 0, nullptr, 0, C, 32, Cs, N2);
    conv_launch<32, 32>(Cs, 32, nbr2, cW32 + 5 * S32, bn32 + 6 * 64, X2, 32, nullptr, 0, cat2 + 32, 64, cat2s + 32, N2);
    conv_launch<64, 32>(cat2s, 64, nbr2, cW6432 + 1 * S6432, bn32 + 12 * 64, nullptr, 0, cat2, 64, Dm, 32, Dms, N2);

    // ---- Decoder level 1 ----
    conv_launch<32, 32>(Dms, 32, nbri2, cW32 + 6 * S32, bn32 + 7 * 64, nullptr, 0, nullptr, 0, cat1, 64, cat1s, N1);
    conv_launch<32, 32>(X1s, 32, nbr1, cW32 + 7 * S32, bn32 + 8 * 64, nullptr, 0, nullptr, 0, A, 32, As, N1);
    conv_launch<32, 32>(As, 32, nbr1, cW32 + 8 * S32, bn32 + 9 * 64, X1, 32, nullptr, 0, cat1 + 32, 64, cat1s + 32, N1);
    conv_launch<64, 32>(cat1s, 64, nbr1, cW6432 + 2 * S6432, bn32 + 13 * 64, nullptr, 0, cat1, 64, A, 32, As, N1);

    // ---- Head ----
    conv_launch<32, 32>(As, 32, nbr1, cW32 + 9 * S32, bn32 + 10 * 64, nullptr, 0, nullptr, 0, outp, 32, nullptr, N1);
}